// round 2
// baseline (speedup 1.0000x reference)
#include <cuda_runtime.h>
#include <cstdint>

#define VOCAB 14
#define EMBED 10
#define HID   50
#define HP    64          // padded unit slots
#define SROW  52          // sH row stride in float2 (416B, 16B-aligned rows)
#define TLEN  2048
#define NBATCH 4096

typedef unsigned long long ull;

// Precomputed tables (global; L1-resident during main loop)
// gWk[k][u] = (0.5*Wi, 0.5*Wf, Wg, 0.5*Wo) at [k*HP + u]   (i,f,o pre-scaled for sigmoid-via-tanh)
// gXT[v][u] = per-token gate init, same per-gate scaling
__device__ float4 gWk[HID * HP];
__device__ float4 gXT[VOCAB * HP];
__device__ float  gq[HID];
__device__ float  gc0;

// ---------------------------------------------------------------------------
__global__ void prep_kernel(const float* __restrict__ emb,
                            const float* __restrict__ W_ih,
                            const float* __restrict__ W_hh,
                            const float* __restrict__ b_ih,
                            const float* __restrict__ b_hh,
                            const float* __restrict__ W1,
                            const float* __restrict__ b1,
                            const float* __restrict__ W2,
                            const float* __restrict__ b2)
{
    int tid = threadIdx.x;

    for (int i = tid; i < HID * HP; i += blockDim.x) {
        int k = i / HP, u = i % HP;
        float4 w = make_float4(0.f, 0.f, 0.f, 0.f);
        if (u < HID) {
            w.x = 0.5f * W_hh[(0 * HID + u) * HID + k];   // i
            w.y = 0.5f * W_hh[(1 * HID + u) * HID + k];   // f
            w.z =        W_hh[(2 * HID + u) * HID + k];   // g
            w.w = 0.5f * W_hh[(3 * HID + u) * HID + k];   // o
        }
        gWk[i] = w;
    }

    for (int i = tid; i < VOCAB * HP; i += blockDim.x) {
        int v = i / HP, u = i % HP;
        float4 x = make_float4(0.f, 0.f, 0.f, 0.f);
        if (u < HID) {
            float* px = reinterpret_cast<float*>(&x);
            #pragma unroll
            for (int g = 0; g < 4; g++) {
                int c = g * HID + u;
                float s = b_ih[c] + b_hh[c];
                #pragma unroll
                for (int e = 0; e < EMBED; e++)
                    s += emb[v * EMBED + e] * W_ih[c * EMBED + e];
                px[g] = (g == 2) ? s : 0.5f * s;          // pre-scale i,f,o
            }
        }
        gXT[i] = x;
    }

    for (int u = tid; u < HID; u += blockDim.x) {
        float s = 0.f;
        for (int m = 0; m < HID; m++) s += W2[m] * W1[m * HID + u];
        gq[u] = s;
    }
    if (tid == 0) {
        float s = b2[0];
        for (int m = 0; m < HID; m++) s += W2[m] * b1[m];
        gc0 = s;
    }
}

// ---------------------------------------------------------------------------
__device__ __forceinline__ ull ffma2(ull a, ull b, ull c) {
    ull d;
    asm("fma.rn.f32x2 %0, %1, %2, %3;" : "=l"(d) : "l"(a), "l"(b), "l"(c));
    return d;
}
__device__ __forceinline__ ull add2(ull a, ull b) {
    ull d;
    asm("add.rn.f32x2 %0, %1, %2;" : "=l"(d) : "l"(a), "l"(b));
    return d;
}
__device__ __forceinline__ float lo_(ull v) { return __uint_as_float((unsigned)v); }
__device__ __forceinline__ float hi_(ull v) { return __uint_as_float((unsigned)(v >> 32)); }

__device__ __forceinline__ float tanhfast(float x) {
    float y;
    asm("tanh.approx.f32 %0, %1;" : "=f"(y) : "f"(x));
    return y;
}
// gate already pre-scaled by 0.5: sigma(2y) = 0.5*tanh(y)+0.5
__device__ __forceinline__ float sigp(float y) { return fmaf(0.5f, tanhfast(y), 0.5f); }

// ---------------------------------------------------------------------------
// CTA = 2 warps, 8 batch rows. Warps split the k-reduction (0..25 / 26..49),
// exchange partial gate sums via SMEM, each finalizes 4 rows' epilogue.
// Lane L owns units {L, L+32}; f32x2 packs (i,f) and (g,o); sH holds (h,h)
// duplicated so one LDS.128 broadcast serves two k's of FFMA2 splats.
// ---------------------------------------------------------------------------
__global__ __launch_bounds__(64) void lstm_kernel(const int* __restrict__ tokens,
                                                  float* __restrict__ out)
{
    __shared__ __align__(16) float2 sH[8][SROW];      // duplicated (h,h), [b][k]
    __shared__ ull sRed[2][4][4][32];                 // [ownerWarp][j][acc][lane]

    const int lane = threadIdx.x & 31;
    const int w    = threadIdx.x >> 5;
    const int b0   = blockIdx.x * 8;
    const int myb0 = w * 4;                           // local batches owned: myb0..+3
    const int u1   = lane;
    const int u2   = lane + 32;
    const bool live2 = (u2 < HID);

    // zero h state
    for (int i = threadIdx.x; i < 8 * SROW; i += 64)
        (&sH[0][0])[i] = make_float2(0.f, 0.f);
    __syncthreads();

    float c1[4], c2[4];
    #pragma unroll
    for (int j = 0; j < 4; j++) { c1[j] = 0.f; c2[j] = 0.f; }

    const int kb = w ? 26 : 0;
    const int ke = w ? 50 : 26;

    const float4* __restrict__ Wp = gWk;
    const float4* __restrict__ Xp = gXT;

    const int* tp[4];
    int tk[4];
    #pragma unroll
    for (int j = 0; j < 4; j++) {
        tp[j] = tokens + (size_t)(b0 + myb0 + j) * TLEN;
        tk[j] = __ldg(tp[j]);
    }

    for (int t = 0; t < TLEN; ++t) {
        // prefetch next tokens (own rows)
        const int t2 = (t + 1 < TLEN) ? t + 1 : t;
        int tkn[4];
        #pragma unroll
        for (int j = 0; j < 4; j++) tkn[j] = __ldg(tp[j] + t2);

        // accumulators for ALL 8 local batches (partial k-sums);
        // own batches start from the token gate-init, others from zero
        ull a1if[8], a1go[8], a2if[8], a2go[8];
        #pragma unroll
        for (int b = 0; b < 8; b++) { a1if[b] = 0; a1go[b] = 0; a2if[b] = 0; a2go[b] = 0; }
        #pragma unroll
        for (int j = 0; j < 4; j++) {
            ulonglong2 v0 = *reinterpret_cast<const ulonglong2*>(Xp + tk[j] * HP + u1);
            ulonglong2 v1 = *reinterpret_cast<const ulonglong2*>(Xp + tk[j] * HP + u2);
            a1if[myb0 + j] = v0.x;  a1go[myb0 + j] = v0.y;
            a2if[myb0 + j] = v1.x;  a2go[myb0 + j] = v1.y;
        }

        // partial recurrent matvec over this warp's k-slice, two k per iter
        #pragma unroll 3
        for (int k = kb; k < ke; k += 2) {
            ulonglong2 wA0 = *reinterpret_cast<const ulonglong2*>(Wp + k * HP + u1);
            ulonglong2 wA1 = *reinterpret_cast<const ulonglong2*>(Wp + k * HP + u2);
            ulonglong2 wB0 = *reinterpret_cast<const ulonglong2*>(Wp + (k + 1) * HP + u1);
            ulonglong2 wB1 = *reinterpret_cast<const ulonglong2*>(Wp + (k + 1) * HP + u2);
            #pragma unroll
            for (int b = 0; b < 8; b++) {
                ulonglong2 hh = *reinterpret_cast<const ulonglong2*>(&sH[b][k]); // (hk,hk),(hk+1,hk+1)
                a1if[b] = ffma2(wA0.x, hh.x, a1if[b]);
                a1go[b] = ffma2(wA0.y, hh.x, a1go[b]);
                a2if[b] = ffma2(wA1.x, hh.x, a2if[b]);
                a2go[b] = ffma2(wA1.y, hh.x, a2go[b]);
                a1if[b] = ffma2(wB0.x, hh.y, a1if[b]);
                a1go[b] = ffma2(wB0.y, hh.y, a1go[b]);
                a2if[b] = ffma2(wB1.x, hh.y, a2if[b]);
                a2go[b] = ffma2(wB1.y, hh.y, a2go[b]);
            }
        }

        // hand partials for the other warp's batches over SMEM
        {
            const int ow = 1 - w;
            #pragma unroll
            for (int j = 0; j < 4; j++) {
                int b = ow * 4 + j;
                sRed[ow][j][0][lane] = a1if[b];
                sRed[ow][j][1][lane] = a1go[b];
                sRed[ow][j][2][lane] = a2if[b];
                sRed[ow][j][3][lane] = a2go[b];
            }
        }
        __syncthreads();

        // finalize own 4 batches
        #pragma unroll
        for (int j = 0; j < 4; j++) {
            const int b = myb0 + j;
            ull gif  = add2(a1if[b], sRed[w][j][0][lane]);
            ull ggo  = add2(a1go[b], sRed[w][j][1][lane]);
            ull gif2 = add2(a2if[b], sRed[w][j][2][lane]);
            ull ggo2 = add2(a2go[b], sRed[w][j][3][lane]);
            const bool live = (tk[j] != 0);
            {   // unit u1
                float i = sigp(lo_(gif));
                float f = sigp(hi_(gif));
                float g = tanhfast(lo_(ggo));
                float o = sigp(hi_(ggo));
                float cn = fmaf(f, c1[j], i * g);
                float hn = o * tanhfast(cn);
                if (live) { c1[j] = cn; sH[b][u1] = make_float2(hn, hn); }
            }
            if (live2) {   // unit u2
                float i = sigp(lo_(gif2));
                float f = sigp(hi_(gif2));
                float g = tanhfast(lo_(ggo2));
                float o = sigp(hi_(ggo2));
                float cn = fmaf(f, c2[j], i * g);
                float hn = o * tanhfast(cn);
                if (live) { c2[j] = cn; sH[b][u2] = make_float2(hn, hn); }
            }
        }
        __syncthreads();

        #pragma unroll
        for (int j = 0; j < 4; j++) tk[j] = tkn[j];
    }

    // collapsed MLP head on own batches (accurate sigmoid)
    if (lane < 4) {
        const int b = myb0 + lane;
        float s = gc0;
        #pragma unroll 10
        for (int k = 0; k < HID; k++) s += gq[k] * sH[b][k].x;
        out[b0 + b] = 1.0f / (1.0f + __expf(-s));
    }
}

// ---------------------------------------------------------------------------
extern "C" void kernel_launch(void* const* d_in, const int* in_sizes, int n_in,
                              void* d_out, int out_size)
{
    const int*   tokens = (const int*)  d_in[0];
    const float* emb    = (const float*)d_in[1];
    const float* W_ih   = (const float*)d_in[2];
    const float* W_hh   = (const float*)d_in[3];
    const float* b_ih   = (const float*)d_in[4];
    const float* b_hh   = (const float*)d_in[5];
    const float* W1     = (const float*)d_in[6];
    const float* b1     = (const float*)d_in[7];
    const float* W2     = (const float*)d_in[8];
    const float* b2     = (const float*)d_in[9];
    float* out = (float*)d_out;

    prep_kernel<<<1, 256>>>(emb, W_ih, W_hh, b_ih, b_hh, W1, b1, W2, b2);
    lstm_kernel<<<NBATCH / 8, 64>>>(tokens, out);
}

// round 3
// speedup vs baseline: 2.7778x; 2.7778x over previous
#include <cuda_runtime.h>
#include <cstdint>

#define VOCAB 14
#define EMBED 10
#define HID   50
#define HP    64          // padded unit slots
#define SROW  52          // sH row stride in float2
#define TLEN  2048
#define NBATCH 4096
#define ROWS  4           // batch rows per warp

typedef unsigned long long ull;

// gWk[k][u] = (0.5*Wi, 0.5*Wf, Wg, 0.5*Wo)  (i,f,o pre-scaled for sigmoid-via-tanh)
// gXT[v][u] = per-token gate init with same scaling
__device__ float4 gWk[HID * HP];
__device__ float4 gXT[VOCAB * HP];
__device__ float  gq[HID];
__device__ float  gc0;

// ---------------------------------------------------------------------------
__global__ void prep_kernel(const float* __restrict__ emb,
                            const float* __restrict__ W_ih,
                            const float* __restrict__ W_hh,
                            const float* __restrict__ b_ih,
                            const float* __restrict__ b_hh,
                            const float* __restrict__ W1,
                            const float* __restrict__ b1,
                            const float* __restrict__ W2,
                            const float* __restrict__ b2)
{
    int tid = threadIdx.x;

    for (int i = tid; i < HID * HP; i += blockDim.x) {
        int k = i / HP, u = i % HP;
        float4 w = make_float4(0.f, 0.f, 0.f, 0.f);
        if (u < HID) {
            w.x = 0.5f * W_hh[(0 * HID + u) * HID + k];
            w.y = 0.5f * W_hh[(1 * HID + u) * HID + k];
            w.z =        W_hh[(2 * HID + u) * HID + k];
            w.w = 0.5f * W_hh[(3 * HID + u) * HID + k];
        }
        gWk[i] = w;
    }

    for (int i = tid; i < VOCAB * HP; i += blockDim.x) {
        int v = i / HP, u = i % HP;
        float4 x = make_float4(0.f, 0.f, 0.f, 0.f);
        if (u < HID) {
            float* px = reinterpret_cast<float*>(&x);
            #pragma unroll
            for (int g = 0; g < 4; g++) {
                int c = g * HID + u;
                float s = b_ih[c] + b_hh[c];
                #pragma unroll
                for (int e = 0; e < EMBED; e++)
                    s += emb[v * EMBED + e] * W_ih[c * EMBED + e];
                px[g] = (g == 2) ? s : 0.5f * s;
            }
        }
        gXT[i] = x;
    }

    for (int u = tid; u < HID; u += blockDim.x) {
        float s = 0.f;
        for (int m = 0; m < HID; m++) s += W2[m] * W1[m * HID + u];
        gq[u] = s;
    }
    if (tid == 0) {
        float s = b2[0];
        for (int m = 0; m < HID; m++) s += W2[m] * b1[m];
        gc0 = s;
    }
}

// ---------------------------------------------------------------------------
__device__ __forceinline__ ull ffma2(ull a, ull b, ull c) {
    ull d;
    asm("fma.rn.f32x2 %0, %1, %2, %3;" : "=l"(d) : "l"(a), "l"(b), "l"(c));
    return d;
}
__device__ __forceinline__ float lo_(ull v) { return __uint_as_float((unsigned)v); }
__device__ __forceinline__ float hi_(ull v) { return __uint_as_float((unsigned)(v >> 32)); }

__device__ __forceinline__ float tanhfast(float x) {
    float y;
    asm("tanh.approx.f32 %0, %1;" : "=f"(y) : "f"(x));
    return y;
}
// gate pre-scaled by 0.5: sigma(2y) = 0.5*tanh(y)+0.5
__device__ __forceinline__ float sigp(float y) { return fmaf(0.5f, tanhfast(y), 0.5f); }

// ---------------------------------------------------------------------------
// 1 warp per CTA, 4 batch rows, fully warp-autonomous recurrence.
// Lane L owns units {L, L+32}; f32x2 packs (i,f) and (g,o) gate pairs.
// sH holds (h,h) duplicated: one LDS.128 gives the splat for two k's.
// ---------------------------------------------------------------------------
__global__ __launch_bounds__(32) void lstm_kernel(const int* __restrict__ tokens,
                                                  float* __restrict__ out)
{
    __shared__ __align__(16) float2 sH[ROWS][SROW];

    const int lane = threadIdx.x;
    const int b0   = blockIdx.x * ROWS;
    const int u1   = lane;
    const int u2   = lane + 32;
    const bool live2 = (u2 < HID);

    // zero h state (incl. pad slots)
    for (int i = lane; i < ROWS * SROW; i += 32)
        (&sH[0][0])[i] = make_float2(0.f, 0.f);
    __syncwarp();

    float c1[ROWS], c2[ROWS];
    #pragma unroll
    for (int j = 0; j < ROWS; j++) { c1[j] = 0.f; c2[j] = 0.f; }

    const float4* __restrict__ Wp = gWk;
    const float4* __restrict__ Xp = gXT;

    const int* tp[ROWS];
    int tk[ROWS];
    #pragma unroll
    for (int j = 0; j < ROWS; j++) {
        tp[j] = tokens + (size_t)(b0 + j) * TLEN;
        tk[j] = __ldg(tp[j]);
    }

    for (int t = 0; t < TLEN; ++t) {
        const int t2 = (t + 1 < TLEN) ? t + 1 : t;
        int tkn[ROWS];
        #pragma unroll
        for (int j = 0; j < ROWS; j++) tkn[j] = __ldg(tp[j] + t2);

        // accumulators init from token gate-init table
        ull a1if[ROWS], a1go[ROWS], a2if[ROWS], a2go[ROWS];
        #pragma unroll
        for (int j = 0; j < ROWS; j++) {
            ulonglong2 v0 = __ldg(reinterpret_cast<const ulonglong2*>(Xp + tk[j] * HP + u1));
            ulonglong2 v1 = __ldg(reinterpret_cast<const ulonglong2*>(Xp + tk[j] * HP + u2));
            a1if[j] = v0.x;  a1go[j] = v0.y;
            a2if[j] = v1.x;  a2go[j] = v1.y;
        }

        // recurrent matvec, two k per iteration, fully unrolled
        #pragma unroll
        for (int k = 0; k < HID; k += 2) {
            ulonglong2 wA0 = __ldg(reinterpret_cast<const ulonglong2*>(Wp + k * HP + u1));
            ulonglong2 wA1 = __ldg(reinterpret_cast<const ulonglong2*>(Wp + k * HP + u2));
            ulonglong2 wB0 = __ldg(reinterpret_cast<const ulonglong2*>(Wp + (k + 1) * HP + u1));
            ulonglong2 wB1 = __ldg(reinterpret_cast<const ulonglong2*>(Wp + (k + 1) * HP + u2));
            #pragma unroll
            for (int j = 0; j < ROWS; j++) {
                ulonglong2 hh = *reinterpret_cast<const ulonglong2*>(&sH[j][k]);
                a1if[j] = ffma2(wA0.x, hh.x, a1if[j]);
                a1go[j] = ffma2(wA0.y, hh.x, a1go[j]);
                a2if[j] = ffma2(wA1.x, hh.x, a2if[j]);
                a2go[j] = ffma2(wA1.y, hh.x, a2go[j]);
                a1if[j] = ffma2(wB0.x, hh.y, a1if[j]);
                a1go[j] = ffma2(wB0.y, hh.y, a1go[j]);
                a2if[j] = ffma2(wB1.x, hh.y, a2if[j]);
                a2go[j] = ffma2(wB1.y, hh.y, a2go[j]);
            }
        }

        __syncwarp();    // reads of sH done

        #pragma unroll
        for (int j = 0; j < ROWS; j++) {
            const bool live = (tk[j] != 0);
            {   // unit u1
                float i = sigp(lo_(a1if[j]));
                float f = sigp(hi_(a1if[j]));
                float g = tanhfast(lo_(a1go[j]));
                float o = sigp(hi_(a1go[j]));
                float cn = fmaf(f, c1[j], i * g);
                float hn = o * tanhfast(cn);
                if (live) { c1[j] = cn; sH[j][u1] = make_float2(hn, hn); }
            }
            if (live2) {   // unit u2
                float i = sigp(lo_(a2if[j]));
                float f = sigp(hi_(a2if[j]));
                float g = tanhfast(lo_(a2go[j]));
                float o = sigp(hi_(a2go[j]));
                float cn = fmaf(f, c2[j], i * g);
                float hn = o * tanhfast(cn);
                if (live) { c2[j] = cn; sH[j][u2] = make_float2(hn, hn); }
            }
        }
        __syncwarp();    // stores visible before next step's reads

        #pragma unroll
        for (int j = 0; j < ROWS; j++) tk[j] = tkn[j];
    }

    // collapsed MLP head: out = sigmoid(c0 + q . h_final)   (accurate sigmoid)
    if (lane < ROWS) {
        const int j = lane;
        float s = gc0;
        #pragma unroll 10
        for (int k = 0; k < HID; k++) s += gq[k] * sH[j][k].x;
        out[b0 + j] = 1.0f / (1.0f + __expf(-s));
    }
}

// ---------------------------------------------------------------------------
extern "C" void kernel_launch(void* const* d_in, const int* in_sizes, int n_in,
                              void* d_out, int out_size)
{
    const int*   tokens = (const int*)  d_in[0];
    const float* emb    = (const float*)d_in[1];
    const float* W_ih   = (const float*)d_in[2];
    const float* W_hh   = (const float*)d_in[3];
    const float* b_ih   = (const float*)d_in[4];
    const float* b_hh   = (const float*)d_in[5];
    const float* W1     = (const float*)d_in[6];
    const float* b1     = (const float*)d_in[7];
    const float* W2     = (const float*)d_in[8];
    const float* b2     = (const float*)d_in[9];
    float* out = (float*)d_out;

    prep_kernel<<<1, 256>>>(emb, W_ih, W_hh, b_ih, b_hh, W1, b1, W2, b2);
    lstm_kernel<<<NBATCH / ROWS, 32>>>(tokens, out);
}

// round 4
// speedup vs baseline: 2.9865x; 1.0751x over previous
#include <cuda_runtime.h>
#include <cstdint>

#define VOCAB 14
#define EMBED 10
#define HID   50
#define HP    64          // padded unit slots (cached-k table)
#define KC    14          // k's cached in registers
#define SROW  52          // sH row stride in float2
#define TLEN  2048
#define NBATCH 4096
#define ROWS  4           // batch rows per warp

typedef unsigned long long ull;

// gWk[k][u]  (padded, u<64) : (0.5*Wi, 0.5*Wf, Wg, 0.5*Wo) — used for k<KC (reg-cached)
// gWs[k-KC][u] (compact, u<50): same values — streamed for k>=KC
// gXT[v][u]  : per-token gate init with same scaling
__device__ float4 gWk[HID * HP];
__device__ float4 gWs[(HID - KC) * HID];
__device__ float4 gXT[VOCAB * HP];
__device__ float  gq[HID];
__device__ float  gc0;

// ---------------------------------------------------------------------------
__global__ void prep_kernel(const float* __restrict__ emb,
                            const float* __restrict__ W_ih,
                            const float* __restrict__ W_hh,
                            const float* __restrict__ b_ih,
                            const float* __restrict__ b_hh,
                            const float* __restrict__ W1,
                            const float* __restrict__ b1,
                            const float* __restrict__ W2,
                            const float* __restrict__ b2)
{
    int tid = threadIdx.x;

    for (int i = tid; i < HID * HP; i += blockDim.x) {
        int k = i / HP, u = i % HP;
        float4 w = make_float4(0.f, 0.f, 0.f, 0.f);
        if (u < HID) {
            w.x = 0.5f * W_hh[(0 * HID + u) * HID + k];
            w.y = 0.5f * W_hh[(1 * HID + u) * HID + k];
            w.z =        W_hh[(2 * HID + u) * HID + k];
            w.w = 0.5f * W_hh[(3 * HID + u) * HID + k];
        }
        gWk[i] = w;
    }

    for (int i = tid; i < (HID - KC) * HID; i += blockDim.x) {
        int k = KC + i / HID, u = i % HID;
        float4 w;
        w.x = 0.5f * W_hh[(0 * HID + u) * HID + k];
        w.y = 0.5f * W_hh[(1 * HID + u) * HID + k];
        w.z =        W_hh[(2 * HID + u) * HID + k];
        w.w = 0.5f * W_hh[(3 * HID + u) * HID + k];
        gWs[i] = w;
    }

    for (int i = tid; i < VOCAB * HP; i += blockDim.x) {
        int v = i / HP, u = i % HP;
        float4 x = make_float4(0.f, 0.f, 0.f, 0.f);
        if (u < HID) {
            float* px = reinterpret_cast<float*>(&x);
            #pragma unroll
            for (int g = 0; g < 4; g++) {
                int c = g * HID + u;
                float s = b_ih[c] + b_hh[c];
                #pragma unroll
                for (int e = 0; e < EMBED; e++)
                    s += emb[v * EMBED + e] * W_ih[c * EMBED + e];
                px[g] = (g == 2) ? s : 0.5f * s;
            }
        }
        gXT[i] = x;
    }

    for (int u = tid; u < HID; u += blockDim.x) {
        float s = 0.f;
        for (int m = 0; m < HID; m++) s += W2[m] * W1[m * HID + u];
        gq[u] = s;
    }
    if (tid == 0) {
        float s = b2[0];
        for (int m = 0; m < HID; m++) s += W2[m] * b1[m];
        gc0 = s;
    }
}

// ---------------------------------------------------------------------------
__device__ __forceinline__ ull ffma2(ull a, ull b, ull c) {
    ull d;
    asm("fma.rn.f32x2 %0, %1, %2, %3;" : "=l"(d) : "l"(a), "l"(b), "l"(c));
    return d;
}
__device__ __forceinline__ float lo_(ull v) { return __uint_as_float((unsigned)v); }
__device__ __forceinline__ float hi_(ull v) { return __uint_as_float((unsigned)(v >> 32)); }

__device__ __forceinline__ float tanhfast(float x) {
    float y;
    asm("tanh.approx.f32 %0, %1;" : "=f"(y) : "f"(x));
    return y;
}
// gate pre-scaled by 0.5: sigma(2y) = 0.5*tanh(y)+0.5
__device__ __forceinline__ float sigp(float y) { return fmaf(0.5f, tanhfast(y), 0.5f); }

// ---------------------------------------------------------------------------
// 1 warp per CTA, 4 batch rows, warp-autonomous recurrence.
// Lane L owns units {L, L+32}; f32x2 packs (i,f) and (g,o).
// k<KC: weights live in registers (loaded once). k>=KC: streamed from a
// compact pad-free table. sH holds (h,h) duplicated for broadcast LDS.128.
// ---------------------------------------------------------------------------
__global__ __launch_bounds__(32) void lstm_kernel(const int* __restrict__ tokens,
                                                  float* __restrict__ out)
{
    __shared__ __align__(16) float2 sH[ROWS][SROW];

    const int lane = threadIdx.x;
    const int b0   = blockIdx.x * ROWS;
    const int u1   = lane;
    const int u2   = lane + 32;
    const bool live2 = (u2 < HID);

    for (int i = lane; i < ROWS * SROW; i += 32)
        (&sH[0][0])[i] = make_float2(0.f, 0.f);
    __syncwarp();

    float c1[ROWS], c2[ROWS];
    #pragma unroll
    for (int j = 0; j < ROWS; j++) { c1[j] = 0.f; c2[j] = 0.f; }

    // register-cached weights for k = 0..KC-1
    ull cw[KC * 4];
    #pragma unroll
    for (int k = 0; k < KC; k++) {
        ulonglong2 a = __ldg(reinterpret_cast<const ulonglong2*>(gWk + k * HP + u1));
        ulonglong2 b = __ldg(reinterpret_cast<const ulonglong2*>(gWk + k * HP + u2));
        cw[k * 4 + 0] = a.x;  cw[k * 4 + 1] = a.y;
        cw[k * 4 + 2] = b.x;  cw[k * 4 + 3] = b.y;
    }

    const float4* __restrict__ Xp = gXT;
    const float4* __restrict__ Sp = gWs;

    const int* tp[ROWS];
    int tk[ROWS];
    #pragma unroll
    for (int j = 0; j < ROWS; j++) {
        tp[j] = tokens + (size_t)(b0 + j) * TLEN;
        tk[j] = __ldg(tp[j]);
    }

    for (int t = 0; t < TLEN; ++t) {
        const int t2 = (t + 1 < TLEN) ? t + 1 : t;
        int tkn[ROWS];
        #pragma unroll
        for (int j = 0; j < ROWS; j++) tkn[j] = __ldg(tp[j] + t2);

        // accumulators init from token gate-init table
        ull a1if[ROWS], a1go[ROWS], a2if[ROWS], a2go[ROWS];
        #pragma unroll
        for (int j = 0; j < ROWS; j++) {
            ulonglong2 v0 = __ldg(reinterpret_cast<const ulonglong2*>(Xp + tk[j] * HP + u1));
            ulonglong2 v1 = __ldg(reinterpret_cast<const ulonglong2*>(Xp + tk[j] * HP + u2));
            a1if[j] = v0.x;  a1go[j] = v0.y;
            a2if[j] = v1.x;  a2go[j] = v1.y;
        }

        // ---- cached k's: no memory traffic for weights
        #pragma unroll
        for (int k = 0; k < KC; k += 2) {
            const ull wA0if = cw[k * 4 + 0], wA0go = cw[k * 4 + 1];
            const ull wA1if = cw[k * 4 + 2], wA1go = cw[k * 4 + 3];
            const ull wB0if = cw[k * 4 + 4], wB0go = cw[k * 4 + 5];
            const ull wB1if = cw[k * 4 + 6], wB1go = cw[k * 4 + 7];
            #pragma unroll
            for (int j = 0; j < ROWS; j++) {
                ulonglong2 hh = *reinterpret_cast<const ulonglong2*>(&sH[j][k]);
                a1if[j] = ffma2(wA0if, hh.x, a1if[j]);
                a1go[j] = ffma2(wA0go, hh.x, a1go[j]);
                a2if[j] = ffma2(wA1if, hh.x, a2if[j]);
                a2go[j] = ffma2(wA1go, hh.x, a2go[j]);
                a1if[j] = ffma2(wB0if, hh.y, a1if[j]);
                a1go[j] = ffma2(wB0go, hh.y, a1go[j]);
                a2if[j] = ffma2(wB1if, hh.y, a2if[j]);
                a2go[j] = ffma2(wB1go, hh.y, a2go[j]);
            }
        }

        // ---- streamed k's from compact pad-free table
        #pragma unroll
        for (int k = KC; k < HID; k += 2) {
            const float4* pA = Sp + (k - KC) * HID;
            const float4* pB = pA + HID;
            ulonglong2 wA0 = __ldg(reinterpret_cast<const ulonglong2*>(pA + u1));
            ulonglong2 wB0 = __ldg(reinterpret_cast<const ulonglong2*>(pB + u1));
            ull wA1if = 0, wA1go = 0, wB1if = 0, wB1go = 0;
            if (live2) {
                ulonglong2 a = __ldg(reinterpret_cast<const ulonglong2*>(pA + u2));
                ulonglong2 b = __ldg(reinterpret_cast<const ulonglong2*>(pB + u2));
                wA1if = a.x;  wA1go = a.y;
                wB1if = b.x;  wB1go = b.y;
            }
            #pragma unroll
            for (int j = 0; j < ROWS; j++) {
                ulonglong2 hh = *reinterpret_cast<const ulonglong2*>(&sH[j][k]);
                a1if[j] = ffma2(wA0.x, hh.x, a1if[j]);
                a1go[j] = ffma2(wA0.y, hh.x, a1go[j]);
                a2if[j] = ffma2(wA1if, hh.x, a2if[j]);
                a2go[j] = ffma2(wA1go, hh.x, a2go[j]);
                a1if[j] = ffma2(wB0.x, hh.y, a1if[j]);
                a1go[j] = ffma2(wB0.y, hh.y, a1go[j]);
                a2if[j] = ffma2(wB1if, hh.y, a2if[j]);
                a2go[j] = ffma2(wB1go, hh.y, a2go[j]);
            }
        }

        __syncwarp();

        #pragma unroll
        for (int j = 0; j < ROWS; j++) {
            const bool live = (tk[j] != 0);
            {   // unit u1
                float i = sigp(lo_(a1if[j]));
                float f = sigp(hi_(a1if[j]));
                float g = tanhfast(lo_(a1go[j]));
                float o = sigp(hi_(a1go[j]));
                float cn = fmaf(f, c1[j], i * g);
                float hn = o * tanhfast(cn);
                if (live) { c1[j] = cn; sH[j][u1] = make_float2(hn, hn); }
            }
            if (live2) {   // unit u2
                float i = sigp(lo_(a2if[j]));
                float f = sigp(hi_(a2if[j]));
                float g = tanhfast(lo_(a2go[j]));
                float o = sigp(hi_(a2go[j]));
                float cn = fmaf(f, c2[j], i * g);
                float hn = o * tanhfast(cn);
                if (live) { c2[j] = cn; sH[j][u2] = make_float2(hn, hn); }
            }
        }
        __syncwarp();

        #pragma unroll
        for (int j = 0; j < ROWS; j++) tk[j] = tkn[j];
    }

    // collapsed MLP head: out = sigmoid(c0 + q . h_final)   (accurate sigmoid)
    if (lane < ROWS) {
        const int j = lane;
        float s = gc0;
        #pragma unroll 10
        for (int k = 0; k < HID; k++) s += gq[k] * sH[j][k].x;
        out[b0 + j] = 1.0f / (1.0f + __expf(-s));
    }
}

// ---------------------------------------------------------------------------
extern "C" void kernel_launch(void* const* d_in, const int* in_sizes, int n_in,
                              void* d_out, int out_size)
{
    const int*   tokens = (const int*)  d_in[0];
    const float* emb    = (const float*)d_in[1];
    const float* W_ih   = (const float*)d_in[2];
    const float* W_hh   = (const float*)d_in[3];
    const float* b_ih   = (const float*)d_in[4];
    const float* b_hh   = (const float*)d_in[5];
    const float* W1     = (const float*)d_in[6];
    const float* b1     = (const float*)d_in[7];
    const float* W2     = (const float*)d_in[8];
    const float* b2     = (const float*)d_in[9];
    float* out = (float*)d_out;

    prep_kernel<<<1, 256>>>(emb, W_ih, W_hh, b_ih, b_hh, W1, b1, W2, b2);
    lstm_kernel<<<NBATCH / ROWS, 32>>>(tokens, out);
}